// round 3
// baseline (speedup 1.0000x reference)
#include <cuda_runtime.h>

typedef unsigned long long ull;

__device__ __forceinline__ ull fma2(ull a, ull b, ull c){
    ull d; asm("fma.rn.f32x2 %0, %1, %2, %3;" : "=l"(d) : "l"(a), "l"(b), "l"(c)); return d;
}
__device__ __forceinline__ ull add2(ull a, ull b){
    ull d; asm("add.rn.f32x2 %0, %1, %2;" : "=l"(d) : "l"(a), "l"(b)); return d;
}
__device__ __forceinline__ ull mul2(ull a, ull b){
    ull d; asm("mul.rn.f32x2 %0, %1, %2;" : "=l"(d) : "l"(a), "l"(b)); return d;
}
__device__ __forceinline__ ull pack2(float x){
    ull d; asm("mov.b64 %0, {%1, %1};" : "=l"(d) : "f"(x)); return d;
}

// E=4 experts, D=128, G=16, KF=16, KTOP=2. Features/row: 80.
// Output: [embedding B*512][raw_weights B*4][mask B*4] float32.
// 10 warps = 2 row-streams x 5 balanced jobs (32 fma2/row each):
//   job0: fourier cols 0..63    job1: fourier cols 64..127
//   job2: spline-h0 + gauss-h0  job3: gauss-h1 + wavelet-h0
//   job4: wavelet-h1 + spline-h1

__global__ __launch_bounds__(320, 2)
void mote_kernel(
    const float* __restrict__ timestamp,   // [B,1]
    const float* __restrict__ aux,         // [B,16]
    const float* __restrict__ router_W,    // [17,4]
    const float* __restrict__ router_b,    // [4]
    const float* __restrict__ freqs,       // [16]
    const float* __restrict__ fourier_W,   // [32,128]
    const float* __restrict__ knots,       // [16]
    const float* __restrict__ spline_W,    // [16,128]
    const float* __restrict__ centers,     // [16]
    const float* __restrict__ gauss_W,     // [16,128]
    const float* __restrict__ wav_centers, // [16]
    const float* __restrict__ wav_scales,  // [16]
    const float* __restrict__ wavelet_W,   // [16,128]
    float* __restrict__ out,
    int B)
{
    __shared__ __align__(16) float2 sFeat[64 * 80];   // raw features, duplicated (v,v)
    __shared__ float sDispP[4 * 64];                  // planar dispatch weights per category
    __shared__ float uC[80], uM[80], uPB[80];         // unified feature constants

    const int tid  = threadIdx.x;
    const int wid  = tid >> 5;
    const int lane = tid & 31;

    // ---- one-time unified feature tables ----
    if (tid < 80){
        int j = tid; float C = 0.f, M, PB = 0.f;
        if (j < 16)      { M = freqs[j]; }                                   // sin(t*f)
        else if (j < 32) { M = freqs[j-16]; PB = 1.5707963267949f; }         // cos = sin(+pi/2)
        else if (j < 48) { C = knots[j-32];   M = 5.3033008589f; }           // 3.75*sqrt(2)
        else if (j < 64) { C = centers[j-48]; M = 1.41421356237f; }          // sqrt(2)
        else             { C = wav_centers[j-64]; M = __fdividef(1.f, wav_scales[j-64]); PB = 1.f; }
        uC[j] = C; uM[j] = M; uPB[j] = PB;
    }

    // ---- phase-2 job setup (per warp) ----
    const int job  = wid % 5;
    const int strm = wid / 5;
    const ull *pA, *pB;
    int featA = 0, featB = 16, catA = 0, catB = 0, dstA = 0, dstB = 0;
    switch (job){
      case 0: pA = (const ull*)fourier_W + lane;      pB = pA + 16*64;
              dstA = lane; break;
      case 1: pA = (const ull*)fourier_W + 32 + lane; pB = pA + 16*64;
              dstA = 32 + lane; break;
      case 2: pA = (const ull*)spline_W  + lane;      pB = (const ull*)gauss_W + lane;
              featA = 32; featB = 48; catA = 1; catB = 2; dstA = 64  + lane; dstB = 128 + lane; break;
      case 3: pA = (const ull*)gauss_W   + 32 + lane; pB = (const ull*)wavelet_W + lane;
              featA = 48; featB = 64; catA = 2; catB = 3; dstA = 160 + lane; dstB = 192 + lane; break;
      default:pA = (const ull*)wavelet_W + 32 + lane; pB = (const ull*)spline_W + 32 + lane;
              featA = 64; featB = 32; catA = 3; catB = 1; dstA = 224 + lane; dstB = 96  + lane; break;
    }
    ull wA[16], wB[16];
    #pragma unroll
    for (int i = 0; i < 16; i++){ wA[i] = pA[(size_t)i * 64]; wB[i] = pB[(size_t)i * 64]; }

    __syncthreads();   // tables ready

    // stage-B (feature) mapping: thread owns feature j0 for 16 rows
    const int q  = tid / 80;            // 0..3
    const int j0 = tid - q * 80;        // 0..79
    const float C = uC[j0], M = uM[j0], PB = uPB[j0];
    const bool trig = (j0 < 32);
    const int  cat  = (j0 < 32) ? 0 : (j0 < 48) ? 1 : (j0 < 64) ? 2 : 3;

    // stage-A (router) mapping: 4 threads/row, first 256 threads
    const int s4  = tid & 3;
    const int lr4 = tid >> 2;
    const unsigned gb = lane & 28;

    const size_t W_OFF = (size_t)B * 512;
    const size_t M_OFF = W_OFF + (size_t)B * 4;
    const int numBatches = B >> 6;   // 64 rows per batch

    for (int batch = blockIdx.x; batch < numBatches; batch += gridDim.x){
        const int rowBase = batch << 6;
        __syncthreads();   // protect smem reuse

        // ================= stage A: router + w/mask (tid < 256) =============
        if (tid < 256){
            const int row = rowBase + lr4;
            const float t = timestamp[row];
            float logit = router_b[s4] + t * router_W[s4];
            const float4* a4 = (const float4*)(aux + (size_t)row * 16);
            float4 x0 = a4[0], x1 = a4[1], x2 = a4[2], x3 = a4[3];
            logit += x0.x*router_W[ 4+s4] + x0.y*router_W[ 8+s4] + x0.z*router_W[12+s4] + x0.w*router_W[16+s4];
            logit += x1.x*router_W[20+s4] + x1.y*router_W[24+s4] + x1.z*router_W[28+s4] + x1.w*router_W[32+s4];
            logit += x2.x*router_W[36+s4] + x2.y*router_W[40+s4] + x2.z*router_W[44+s4] + x2.w*router_W[48+s4];
            logit += x3.x*router_W[52+s4] + x3.y*router_W[56+s4] + x3.z*router_W[60+s4] + x3.w*router_W[64+s4];

            float l0 = __shfl_sync(0xffffffffu, logit, gb + 0);
            float l1 = __shfl_sync(0xffffffffu, logit, gb + 1);
            float l2 = __shfl_sync(0xffffffffu, logit, gb + 2);
            float l3 = __shfl_sync(0xffffffffu, logit, gb + 3);
            float m  = fmaxf(fmaxf(l0, l1), fmaxf(l2, l3));
            float e0 = __expf(l0 - m), e1 = __expf(l1 - m);
            float e2 = __expf(l2 - m), e3 = __expf(l3 - m);
            float inv = __fdividef(1.0f, e0 + e1 + e2 + e3);
            float w0 = e0*inv, w1 = e1*inv, w2 = e2*inv, w3 = e3*inv;

            int r0 = (w1 >  w0) + (w2 >  w0) + (w3 >  w0);
            int r1 = (w0 >= w1) + (w2 >  w1) + (w3 >  w1);
            int r2 = (w0 >= w2) + (w1 >= w2) + (w3 >  w2);
            int r3 = (w0 >= w3) + (w1 >= w3) + (w2 >= w3);

            float ws = (s4==0) ? w0 : (s4==1) ? w1 : (s4==2) ? w2 : w3;
            int   rs = (s4==0) ? r0 : (s4==1) ? r1 : (s4==2) ? r2 : r3;
            sDispP[s4*64 + lr4] = (rs < 2) ? ws : 0.f;
            out[W_OFF + (size_t)row*4 + s4] = ws;
            out[M_OFF + (size_t)row*4 + s4] = (rs < 2) ? 1.0f : 0.0f;
        }

        // ================= stage B: raw features (all 320 threads) ==========
        #pragma unroll 4
        for (int k = 0; k < 16; k++){
            const int lrow = q * 16 + k;
            const float t = timestamp[rowBase + lrow];
            float v;
            if (trig){
                v = __sinf(fmaf(t, M, PB));
            } else {
                float u  = (t - C) * M;
                float uu = u * u;
                v = fmaf(-PB, uu, 1.0f) * __expf(-0.5f * uu);
            }
            sFeat[lrow * 80 + j0] = make_float2(v, v);
        }
        __syncthreads();

        // ================= phase 2: matvecs (warp = job, 32 rows/stream) ====
        const int rb = strm * 32;
        if (job < 2){
            #pragma unroll 1
            for (int r = 0; r < 32; r++){
                const int lrow = rb + r;
                ull* dst = (ull*)out + (size_t)(rowBase + lrow) * 256 + dstA;
                const float sel = sDispP[lrow];          // fourier = category 0
                if (sel != 0.f){
                    const float2* feat = sFeat + lrow * 80;
                    ull a0 = 0, a1 = 0, a2 = 0, a3 = 0;
                    #pragma unroll
                    for (int i = 0; i < 8; i++){
                        ulonglong2 f0 = *(const ulonglong2*)(feat + 2*i);
                        ulonglong2 f1 = *(const ulonglong2*)(feat + 16 + 2*i);
                        a0 = fma2(wA[2*i],   f0.x, a0);
                        a1 = fma2(wA[2*i+1], f0.y, a1);
                        a2 = fma2(wB[2*i],   f1.x, a2);
                        a3 = fma2(wB[2*i+1], f1.y, a3);
                    }
                    *dst = mul2(add2(add2(a0, a1), add2(a2, a3)), pack2(sel));
                } else *dst = 0ull;
            }
        } else {
            #pragma unroll 1
            for (int r = 0; r < 32; r++){
                const int lrow = rb + r;
                ull* o = (ull*)out + (size_t)(rowBase + lrow) * 256;
                const float2* feat = sFeat + lrow * 80;

                const float selA = sDispP[catA*64 + lrow];
                if (selA != 0.f){
                    ull a0 = 0, a1 = 0;
                    #pragma unroll
                    for (int i = 0; i < 8; i++){
                        ulonglong2 f = *(const ulonglong2*)(feat + featA + 2*i);
                        a0 = fma2(wA[2*i],   f.x, a0);
                        a1 = fma2(wA[2*i+1], f.y, a1);
                    }
                    o[dstA] = mul2(add2(a0, a1), pack2(selA));
                } else o[dstA] = 0ull;

                const float selB = sDispP[catB*64 + lrow];
                if (selB != 0.f){
                    ull a0 = 0, a1 = 0;
                    #pragma unroll
                    for (int i = 0; i < 8; i++){
                        ulonglong2 f = *(const ulonglong2*)(feat + featB + 2*i);
                        a0 = fma2(wB[2*i],   f.x, a0);
                        a1 = fma2(wB[2*i+1], f.y, a1);
                    }
                    o[dstB] = mul2(add2(a0, a1), pack2(selB));
                } else o[dstB] = 0ull;
            }
        }
    }
}

extern "C" void kernel_launch(void* const* d_in, const int* in_sizes, int n_in,
                              void* d_out, int out_size)
{
    const float* timestamp   = (const float*)d_in[0];
    const float* aux         = (const float*)d_in[1];
    const float* router_W    = (const float*)d_in[2];
    const float* router_b    = (const float*)d_in[3];
    const float* freqs       = (const float*)d_in[4];
    const float* fourier_W   = (const float*)d_in[5];
    const float* knots       = (const float*)d_in[6];
    const float* spline_W    = (const float*)d_in[7];
    const float* centers     = (const float*)d_in[8];
    const float* gauss_W     = (const float*)d_in[9];
    const float* wav_centers = (const float*)d_in[10];
    const float* wav_scales  = (const float*)d_in[11];
    const float* wavelet_W   = (const float*)d_in[12];
    float* out = (float*)d_out;

    const int B = in_sizes[0];

    mote_kernel<<<296, 320>>>(timestamp, aux, router_W, router_b, freqs,
                              fourier_W, knots, spline_W, centers, gauss_W,
                              wav_centers, wav_scales, wavelet_W, out, B);
}

// round 4
// speedup vs baseline: 1.0698x; 1.0698x over previous
#include <cuda_runtime.h>

typedef unsigned long long ull;

__device__ __forceinline__ ull fma2(ull a, ull b, ull c){
    ull d; asm("fma.rn.f32x2 %0, %1, %2, %3;" : "=l"(d) : "l"(a), "l"(b), "l"(c)); return d;
}
__device__ __forceinline__ ull add2(ull a, ull b){
    ull d; asm("add.rn.f32x2 %0, %1, %2;" : "=l"(d) : "l"(a), "l"(b)); return d;
}
__device__ __forceinline__ ull mul2(ull a, ull b){
    ull d; asm("mul.rn.f32x2 %0, %1, %2;" : "=l"(d) : "l"(a), "l"(b)); return d;
}
__device__ __forceinline__ ull pack2(float x){
    ull d; asm("mov.b64 %0, {%1, %1};" : "=l"(d) : "f"(x)); return d;
}

// E=4, D=128, G=16, KF=16 (freqs = 1..16), KTOP=2. Features/row: 80.
// sFeat layout per row (stride 82 float2, duplicated (v,v)):
//   f2 [0..31]  : interleaved s1,c1,s2,c2,... (sin/cos of k*t)
//   f2 [32..47] : spline    f2 [48..63] : gauss    f2 [64..79] : wavelet
// Phase 2: 10 warps = 2 row-streams x 5 balanced jobs (32 fma2/row each).

#define FSTRIDE 82

__global__ __launch_bounds__(320, 2)
void mote_kernel(
    const float* __restrict__ timestamp,   // [B,1]
    const float* __restrict__ aux,         // [B,16]
    const float* __restrict__ router_W,    // [17,4]
    const float* __restrict__ router_b,    // [4]
    const float* __restrict__ freqs,       // [16] (= 1..16)
    const float* __restrict__ fourier_W,   // [32,128]
    const float* __restrict__ knots,       // [16] (= linspace(-2,2,16))
    const float* __restrict__ spline_W,    // [16,128]
    const float* __restrict__ centers,     // [16]
    const float* __restrict__ gauss_W,     // [16,128]
    const float* __restrict__ wav_centers, // [16]
    const float* __restrict__ wav_scales,  // [16]
    const float* __restrict__ wavelet_W,   // [16,128]
    float* __restrict__ out,
    int B)
{
    __shared__ __align__(16) float2 sFeat[64 * FSTRIDE];
    __shared__ float sDispP[4 * 64];     // planar dispatch weights [expert][row]
    __shared__ float sTime[64];

    const int tid  = threadIdx.x;
    const int wid  = tid >> 5;
    const int lane = tid & 31;

    // ---------------- phase-2 job setup (per warp) ----------------
    const int job  = wid % 5;
    const int strm = wid / 5;
    ull wA[16], wB[16];
    int featA = 0, featB = 16, catA = 0, catB = 0, dstA = 0, dstB = 0;
    {
        const ull *pA, *pB;
        if (job < 2){
            // fourier halves; weights permuted to match interleaved sin/cos:
            // f2 index m -> W row (m>>1) + 16*(m&1)
            const int co = job * 32;  // column offset in ull units
            #pragma unroll
            for (int i = 0; i < 16; i++){
                int rA = (i >> 1) + ((i & 1) ? 16 : 0);
                int m2 = 16 + i;
                int rB = (m2 >> 1) + ((m2 & 1) ? 16 : 0);
                wA[i] = ((const ull*)fourier_W)[(size_t)rA * 64 + co + lane];
                wB[i] = ((const ull*)fourier_W)[(size_t)rB * 64 + co + lane];
            }
            dstA = co + lane;
        } else {
            switch (job){
              case 2:  pA = (const ull*)spline_W  + lane;      pB = (const ull*)gauss_W + lane;
                       featA = 32; featB = 48; catA = 1; catB = 2; dstA = 64  + lane; dstB = 128 + lane; break;
              case 3:  pA = (const ull*)gauss_W   + 32 + lane; pB = (const ull*)wavelet_W + lane;
                       featA = 48; featB = 64; catA = 2; catB = 3; dstA = 160 + lane; dstB = 192 + lane; break;
              default: pA = (const ull*)wavelet_W + 32 + lane; pB = (const ull*)spline_W + 32 + lane;
                       featA = 64; featB = 32; catA = 3; catB = 1; dstA = 224 + lane; dstB = 96  + lane; break;
            }
            #pragma unroll
            for (int i = 0; i < 16; i++){ wA[i] = pA[(size_t)i * 64]; wB[i] = pB[(size_t)i * 64]; }
        }
    }

    // ---------------- stage-B per-thread constants ----------------
    float bC = 0.f, bI = 0.f;
    if (wid == 4 || wid == 5)      bC = centers[(tid - 128) & 15];
    else if (wid >= 6){ int j = (tid - 192) & 15;
                        bC = wav_centers[j]; bI = __fdividef(1.f, wav_scales[j]); }

    // stage-A mapping: 4 threads per row, first 256 threads
    const int s4  = tid & 3;
    const int lr4 = tid >> 2;
    const unsigned gb = lane & 28;

    const size_t W_OFF = (size_t)B * 512;
    const size_t M_OFF = W_OFF + (size_t)B * 4;
    const int numBatches = B >> 6;   // 64 rows per batch
    const float E_M2 = 0.13533528324f;   // e^-2

    for (int batch = blockIdx.x; batch < numBatches; batch += gridDim.x){
        const int rowBase = batch << 6;
        __syncthreads();   // protect smem reuse (prev phase-2 reads done)

        // ================= stage A: router + w/mask (tid < 256) =============
        if (tid < 256){
            const int row = rowBase + lr4;
            const float t = timestamp[row];
            if (s4 == 0) sTime[lr4] = t;
            float logit = router_b[s4] + t * router_W[s4];
            const float4* a4 = (const float4*)(aux + (size_t)row * 16);
            float4 x0 = a4[0], x1 = a4[1], x2 = a4[2], x3 = a4[3];
            logit += x0.x*router_W[ 4+s4] + x0.y*router_W[ 8+s4] + x0.z*router_W[12+s4] + x0.w*router_W[16+s4];
            logit += x1.x*router_W[20+s4] + x1.y*router_W[24+s4] + x1.z*router_W[28+s4] + x1.w*router_W[32+s4];
            logit += x2.x*router_W[36+s4] + x2.y*router_W[40+s4] + x2.z*router_W[44+s4] + x2.w*router_W[48+s4];
            logit += x3.x*router_W[52+s4] + x3.y*router_W[56+s4] + x3.z*router_W[60+s4] + x3.w*router_W[64+s4];

            float l0 = __shfl_sync(0xffffffffu, logit, gb + 0);
            float l1 = __shfl_sync(0xffffffffu, logit, gb + 1);
            float l2 = __shfl_sync(0xffffffffu, logit, gb + 2);
            float l3 = __shfl_sync(0xffffffffu, logit, gb + 3);
            float m  = fmaxf(fmaxf(l0, l1), fmaxf(l2, l3));
            float e0 = __expf(l0 - m), e1 = __expf(l1 - m);
            float e2 = __expf(l2 - m), e3 = __expf(l3 - m);
            float inv = __fdividef(1.0f, e0 + e1 + e2 + e3);
            float w0 = e0*inv, w1 = e1*inv, w2 = e2*inv, w3 = e3*inv;

            int r0 = (w1 >  w0) + (w2 >  w0) + (w3 >  w0);
            int r1 = (w0 >= w1) + (w2 >  w1) + (w3 >  w1);
            int r2 = (w0 >= w2) + (w1 >= w2) + (w3 >  w2);
            int r3 = (w0 >= w3) + (w1 >= w3) + (w2 >= w3);

            float ws = (s4==0) ? w0 : (s4==1) ? w1 : (s4==2) ? w2 : w3;
            int   rs = (s4==0) ? r0 : (s4==1) ? r1 : (s4==2) ? r2 : r3;
            sDispP[s4*64 + lr4] = (rs < 2) ? ws : 0.f;
            out[W_OFF + (size_t)row*4 + s4] = ws;
            out[M_OFF + (size_t)row*4 + s4] = (rs < 2) ? 1.0f : 0.0f;
        }
        __syncthreads();   // sTime ready

        // ================= stage B: raw features, warp-specialized ==========
        if (wid < 2){
            // --- trig: thread = row; sin/cos ladder, 2 MUFU total ---
            const int row = tid;
            const float t = sTime[row];
            float4* dst = (float4*)(sFeat + row * FSTRIDE);
            float s1 = __sinf(t), c1 = __cosf(t);
            float sk = s1, ck = c1;
            dst[0] = make_float4(s1, s1, c1, c1);
            #pragma unroll
            for (int k = 1; k < 16; k++){
                float sn = fmaf(sk, c1,  ck * s1);
                float cn = fmaf(ck, c1, -sk * s1);
                dst[k] = make_float4(sn, sn, cn, cn);
                sk = sn; ck = cn;
            }
        } else if (wid < 4){
            // --- spline: thread = row; anchored geometric-ratio chain, 3 MUFU ---
            const int row = tid - 64;
            const float t = sTime[row];
            float2* dst = sFeat + row * FSTRIDE + 32;
            const float a = (t + 2.0f) * 3.75f;          // (t - k0)/h, h = 4/15
            int j0 = __float2int_rn(a);
            j0 = max(0, min(15, j0));
            const float d = a - (float)j0;
            const float f0 = __expf(-d * d);
            dst[j0] = make_float2(f0, f0);
            float f = f0, r = __expf(fmaf(2.0f, d, -1.0f));      // exp(2d-1)
            #pragma unroll
            for (int k = 1; k <= 15; k++){
                f *= r; r *= E_M2;
                if (j0 + k <= 15) dst[j0 + k] = make_float2(f, f);
            }
            f = f0; r = __expf(fmaf(-2.0f, d, -1.0f));           // exp(-2d-1)
            #pragma unroll
            for (int k = 1; k <= 15; k++){
                f *= r; r *= E_M2;
                if (j0 - k >= 0) dst[j0 - k] = make_float2(f, f);
            }
        } else if (wid < 6){
            // --- gauss: thread = (feature j, 16-row block) ---
            const int tt = tid - 128;
            const int j  = tt & 15;
            const int r0 = (tt >> 4) << 4;
            #pragma unroll 4
            for (int k = 0; k < 16; k++){
                const int row = r0 + k;
                const float u = sTime[row] - bC;
                const float v = __expf(-u * u);
                sFeat[row * FSTRIDE + 48 + j] = make_float2(v, v);
            }
        } else {
            // --- wavelet: thread = (feature j, 8-row block), 4 warps ---
            const int tt = tid - 192;
            const int j  = tt & 15;
            const int r0 = (tt >> 4) << 3;
            #pragma unroll 4
            for (int k = 0; k < 8; k++){
                const int row = r0 + k;
                const float u  = (sTime[row] - bC) * bI;
                const float uu = u * u;
                const float v  = fmaf(-uu, 1.0f, 1.0f) * __expf(-0.5f * uu);
                sFeat[row * FSTRIDE + 64 + j] = make_float2(v, v);
            }
        }
        __syncthreads();

        // ================= phase 2: matvecs (warp = job, 32 rows/stream) ====
        const int rb = strm * 32;
        if (job < 2){
            #pragma unroll 1
            for (int r = 0; r < 32; r++){
                const int lrow = rb + r;
                ull* dst = (ull*)out + (size_t)(rowBase + lrow) * 256 + dstA;
                const float sel = sDispP[lrow];          // fourier = category 0
                if (sel != 0.f){
                    const float2* feat = sFeat + lrow * FSTRIDE;
                    ull a0 = 0, a1 = 0, a2 = 0, a3 = 0;
                    #pragma unroll
                    for (int i = 0; i < 8; i++){
                        ulonglong2 f0 = *(const ulonglong2*)(feat + 2*i);
                        ulonglong2 f1 = *(const ulonglong2*)(feat + 16 + 2*i);
                        a0 = fma2(wA[2*i],   f0.x, a0);
                        a1 = fma2(wA[2*i+1], f0.y, a1);
                        a2 = fma2(wB[2*i],   f1.x, a2);
                        a3 = fma2(wB[2*i+1], f1.y, a3);
                    }
                    *dst = mul2(add2(add2(a0, a1), add2(a2, a3)), pack2(sel));
                } else *dst = 0ull;
            }
        } else {
            #pragma unroll 1
            for (int r = 0; r < 32; r++){
                const int lrow = rb + r;
                ull* o = (ull*)out + (size_t)(rowBase + lrow) * 256;
                const float2* feat = sFeat + lrow * FSTRIDE;

                const float selA = sDispP[catA*64 + lrow];
                if (selA != 0.f){
                    ull a0 = 0, a1 = 0;
                    #pragma unroll
                    for (int i = 0; i < 8; i++){
                        ulonglong2 f = *(const ulonglong2*)(feat + featA + 2*i);
                        a0 = fma2(wA[2*i],   f.x, a0);
                        a1 = fma2(wA[2*i+1], f.y, a1);
                    }
                    o[dstA] = mul2(add2(a0, a1), pack2(selA));
                } else o[dstA] = 0ull;

                const float selB = sDispP[catB*64 + lrow];
                if (selB != 0.f){
                    ull a0 = 0, a1 = 0;
                    #pragma unroll
                    for (int i = 0; i < 8; i++){
                        ulonglong2 f = *(const ulonglong2*)(feat + featB + 2*i);
                        a0 = fma2(wB[2*i],   f.x, a0);
                        a1 = fma2(wB[2*i+1], f.y, a1);
                    }
                    o[dstB] = mul2(add2(a0, a1), pack2(selB));
                } else o[dstB] = 0ull;
            }
        }
    }
}

extern "C" void kernel_launch(void* const* d_in, const int* in_sizes, int n_in,
                              void* d_out, int out_size)
{
    const float* timestamp   = (const float*)d_in[0];
    const float* aux         = (const float*)d_in[1];
    const float* router_W    = (const float*)d_in[2];
    const float* router_b    = (const float*)d_in[3];
    const float* freqs       = (const float*)d_in[4];
    const float* fourier_W   = (const float*)d_in[5];
    const float* knots       = (const float*)d_in[6];
    const float* spline_W    = (const float*)d_in[7];
    const float* centers     = (const float*)d_in[8];
    const float* gauss_W     = (const float*)d_in[9];
    const float* wav_centers = (const float*)d_in[10];
    const float* wav_scales  = (const float*)d_in[11];
    const float* wavelet_W   = (const float*)d_in[12];
    float* out = (float*)d_out;

    const int B = in_sizes[0];

    mote_kernel<<<296, 320>>>(timestamp, aux, router_W, router_b, freqs,
                              fourier_W, knots, spline_W, centers, gauss_W,
                              wav_centers, wav_scales, wavelet_W, out, B);
}

// round 6
// speedup vs baseline: 1.3032x; 1.2182x over previous
#include <cuda_runtime.h>

typedef unsigned long long ull;

__device__ __forceinline__ ull fma2(ull a, ull b, ull c){
    ull d; asm("fma.rn.f32x2 %0, %1, %2, %3;" : "=l"(d) : "l"(a), "l"(b), "l"(c)); return d;
}
__device__ __forceinline__ ull add2(ull a, ull b){
    ull d; asm("add.rn.f32x2 %0, %1, %2;" : "=l"(d) : "l"(a), "l"(b)); return d;
}
__device__ __forceinline__ ull mul2(ull a, ull b){
    ull d; asm("mul.rn.f32x2 %0, %1, %2;" : "=l"(d) : "l"(a), "l"(b)); return d;
}
__device__ __forceinline__ ull pack2(float x){
    ull d; asm("mov.b64 %0, {%1, %1};" : "=l"(d) : "f"(x)); return d;
}

// E=4, D=128, G=16, KF=16 (freqs = 1..16), KTOP=2. Features/row: 80.
// sFeat per row (stride 82 float2, duplicated (v,v)):
//   f2 [0..31]  : interleaved s1,c1,s2,c2,... (sin/cos of k*t)
//   f2 [32..47] : spline   f2 [48..63] : gauss   f2 [64..79] : wavelet
// Phase 2: 10 warps = 2 row-streams x 5 jobs (32 fma2/row each):
//   job0/1: fourier col-halves (1 category, 1 store)
//   job2/3/4: spline/gauss/wavelet FULL 128 cols (8 LDS feeds 32 fma2, 2 stores)

#define FSTRIDE 82

__global__ __launch_bounds__(320, 2)
void mote_kernel(
    const float* __restrict__ timestamp,   // [B,1]
    const float* __restrict__ aux,         // [B,16]
    const float* __restrict__ router_W,    // [17,4]
    const float* __restrict__ router_b,    // [4]
    const float* __restrict__ freqs,       // [16] (= 1..16)
    const float* __restrict__ fourier_W,   // [32,128]
    const float* __restrict__ knots,       // [16] (= linspace(-2,2,16))
    const float* __restrict__ spline_W,    // [16,128]
    const float* __restrict__ centers,     // [16]
    const float* __restrict__ gauss_W,     // [16,128]
    const float* __restrict__ wav_centers, // [16]
    const float* __restrict__ wav_scales,  // [16]
    const float* __restrict__ wavelet_W,   // [16,128]
    float* __restrict__ out,
    int B)
{
    __shared__ __align__(16) float2 sFeat[64 * FSTRIDE];
    __shared__ float sDispP[4 * 64];     // planar dispatch weights [expert][row]
    __shared__ float sTime[64];

    const int tid  = threadIdx.x;
    const int wid  = tid >> 5;
    const int lane = tid & 31;

    // ---------------- phase-2 job setup (per warp) ----------------
    const int job  = wid % 5;
    const int strm = wid / 5;
    ull wA[16], wB[16];
    int cat = 0, foff = 0, dstA = 0, dstB = 0;
    if (job < 2){
        // fourier halves; weights permuted to interleaved sin/cos order:
        // f2 index m -> W row (m>>1) + 16*(m&1)
        const int co = job * 32;
        #pragma unroll
        for (int i = 0; i < 16; i++){
            int rA = (i >> 1) + ((i & 1) ? 16 : 0);
            int m2 = 16 + i;
            int rB = (m2 >> 1) + ((m2 & 1) ? 16 : 0);
            wA[i] = ((const ull*)fourier_W)[(size_t)rA * 64 + co + lane];
            wB[i] = ((const ull*)fourier_W)[(size_t)rB * 64 + co + lane];
        }
        dstA = co + lane;
    } else {
        cat  = job - 1;                        // 1=spline, 2=gauss, 3=wavelet
        foff = 16 + 16 * cat;                  // 32 / 48 / 64
        const float* Wexp = (cat == 1) ? spline_W : (cat == 2) ? gauss_W : wavelet_W;
        #pragma unroll
        for (int i = 0; i < 16; i++){
            wA[i] = ((const ull*)Wexp)[(size_t)i * 64 + lane];
            wB[i] = ((const ull*)Wexp)[(size_t)i * 64 + 32 + lane];
        }
        dstA = cat * 64 + lane;
        dstB = cat * 64 + 32 + lane;
    }

    // ---------------- stage-B per-thread constants ----------------
    float bC = 0.f, bI = 0.f;
    if (wid == 4 || wid == 5)      bC = centers[(tid - 128) & 15];
    else if (wid >= 6){ int j = (tid - 192) & 15;
                        bC = wav_centers[j]; bI = __fdividef(1.f, wav_scales[j]); }

    // stage-A mapping: 4 threads per row, first 256 threads
    const int s4  = tid & 3;
    const int lr4 = tid >> 2;

    const size_t W_OFF = (size_t)B * 512;
    const size_t M_OFF = W_OFF + (size_t)B * 4;
    const int numBatches = B >> 6;   // 64 rows per batch
    const float E_M2 = 0.13533528324f;   // e^-2

    for (int batch = blockIdx.x; batch < numBatches; batch += gridDim.x){
        const int rowBase = batch << 6;
        __syncthreads();   // prev phase-2 reads done before smem rewrite

        // ================= stage A: router + w/mask (tid < 256) =============
        if (tid < 256){
            const int row = rowBase + lr4;
            const float t = timestamp[row];
            if (s4 == 0) sTime[lr4] = t;

            // cooperative aux dot: thread s4 handles quarter s4
            const float4 xa = ((const float4*)(aux + (size_t)row * 16))[s4];
            const float* Wq = router_W + (1 + 4 * s4) * 4;
            float p0 = xa.x*Wq[0] + xa.y*Wq[4] + xa.z*Wq[8]  + xa.w*Wq[12];
            float p1 = xa.x*Wq[1] + xa.y*Wq[5] + xa.z*Wq[9]  + xa.w*Wq[13];
            float p2 = xa.x*Wq[2] + xa.y*Wq[6] + xa.z*Wq[10] + xa.w*Wq[14];
            float p3 = xa.x*Wq[3] + xa.y*Wq[7] + xa.z*Wq[11] + xa.w*Wq[15];
            if (s4 == 0){
                p0 += t*router_W[0] + router_b[0];
                p1 += t*router_W[1] + router_b[1];
                p2 += t*router_W[2] + router_b[2];
                p3 += t*router_W[3] + router_b[3];
            }
            // quad reduce: after xor1+xor2 every thread holds all 4 logits
            p0 += __shfl_xor_sync(0xffffffffu, p0, 1);
            p1 += __shfl_xor_sync(0xffffffffu, p1, 1);
            p2 += __shfl_xor_sync(0xffffffffu, p2, 1);
            p3 += __shfl_xor_sync(0xffffffffu, p3, 1);
            p0 += __shfl_xor_sync(0xffffffffu, p0, 2);
            p1 += __shfl_xor_sync(0xffffffffu, p1, 2);
            p2 += __shfl_xor_sync(0xffffffffu, p2, 2);
            p3 += __shfl_xor_sync(0xffffffffu, p3, 2);

            float m  = fmaxf(fmaxf(p0, p1), fmaxf(p2, p3));
            float e0 = __expf(p0 - m), e1 = __expf(p1 - m);
            float e2 = __expf(p2 - m), e3 = __expf(p3 - m);
            float inv = __fdividef(1.0f, e0 + e1 + e2 + e3);
            float w0 = e0*inv, w1 = e1*inv, w2 = e2*inv, w3 = e3*inv;

            int r0 = (w1 >  w0) + (w2 >  w0) + (w3 >  w0);
            int r1 = (w0 >= w1) + (w2 >  w1) + (w3 >  w1);
            int r2 = (w0 >= w2) + (w1 >= w2) + (w3 >  w2);
            int r3 = (w0 >= w3) + (w1 >= w3) + (w2 >= w3);

            float ws = (s4==0) ? w0 : (s4==1) ? w1 : (s4==2) ? w2 : w3;
            int   rs = (s4==0) ? r0 : (s4==1) ? r1 : (s4==2) ? r2 : r3;
            sDispP[s4*64 + lr4] = (rs < 2) ? ws : 0.f;
            out[W_OFF + (size_t)row*4 + s4] = ws;
            out[M_OFF + (size_t)row*4 + s4] = (rs < 2) ? 1.0f : 0.0f;
        }
        __syncthreads();   // sTime/sDispP ready

        // ================= stage B: raw features, warp-specialized ==========
        if (wid < 2){
            // trig: thread = row; sin/cos ladder, 2 MUFU
            const int row = tid;
            const float t = sTime[row];
            float4* dst = (float4*)(sFeat + row * FSTRIDE);
            float s1 = __sinf(t), c1 = __cosf(t);
            float sk = s1, ck = c1;
            dst[0] = make_float4(s1, s1, c1, c1);
            #pragma unroll
            for (int k = 1; k < 16; k++){
                float sn = fmaf(sk, c1,  ck * s1);
                float cn = fmaf(ck, c1, -sk * s1);
                dst[k] = make_float4(sn, sn, cn, cn);
                sk = sn; ck = cn;
            }
        } else if (wid < 4){
            // spline: thread = row; anchored geometric-ratio chain, 3 MUFU
            const int row = tid - 64;
            const float t = sTime[row];
            float2* dst = sFeat + row * FSTRIDE + 32;
            const float a = (t + 2.0f) * 3.75f;
            int j0 = __float2int_rn(a);
            j0 = max(0, min(15, j0));
            const float d = a - (float)j0;
            const float f0 = __expf(-d * d);
            dst[j0] = make_float2(f0, f0);
            float f = f0, r = __expf(fmaf(2.0f, d, -1.0f));
            #pragma unroll
            for (int k = 1; k <= 15; k++){
                f *= r; r *= E_M2;
                if (j0 + k <= 15) dst[j0 + k] = make_float2(f, f);
            }
            f = f0; r = __expf(fmaf(-2.0f, d, -1.0f));
            #pragma unroll
            for (int k = 1; k <= 15; k++){
                f *= r; r *= E_M2;
                if (j0 - k >= 0) dst[j0 - k] = make_float2(f, f);
            }
        } else if (wid < 6){
            // gauss: thread = (feature j, 16-row block)
            const int tt = tid - 128;
            const int j  = tt & 15;
            const int r0 = (tt >> 4) << 4;
            #pragma unroll 4
            for (int k = 0; k < 16; k++){
                const int row = r0 + k;
                const float u = sTime[row] - bC;
                const float v = __expf(-u * u);
                sFeat[row * FSTRIDE + 48 + j] = make_float2(v, v);
            }
        } else {
            // wavelet: thread = (feature j, 8-row block), 4 warps
            const int tt = tid - 192;
            const int j  = tt & 15;
            const int r0 = (tt >> 4) << 3;
            #pragma unroll 4
            for (int k = 0; k < 8; k++){
                const int row = r0 + k;
                const float u  = (sTime[row] - bC) * bI;
                const float uu = u * u;
                const float v  = (1.0f - uu) * __expf(-0.5f * uu);
                sFeat[row * FSTRIDE + 64 + j] = make_float2(v, v);
            }
        }
        __syncthreads();

        // ================= phase 2: matvecs (warp = job, 32 rows/stream) ====
        const int rb = strm * 32;
        const float selv = sDispP[cat*64 + rb + lane];     // lane r = row rb+r
        const unsigned act = __ballot_sync(0xffffffffu, selv != 0.f);
        ull* obase = (ull*)out + (size_t)(rowBase + rb) * 256;

        if (job < 2){
            #pragma unroll 2
            for (int r = 0; r < 32; r++){
                ull* o = obase + (size_t)r * 256 + dstA;
                const float s = __shfl_sync(0xffffffffu, selv, r);
                if (act & (1u << r)){
                    const float2* feat = sFeat + (rb + r) * FSTRIDE;
                    ull a0 = 0, a1 = 0, a2 = 0, a3 = 0;
                    #pragma unroll
                    for (int i = 0; i < 8; i++){
                        ulonglong2 f0 = *(const ulonglong2*)(feat + 2*i);
                        ulonglong2 f1 = *(const ulonglong2*)(feat + 16 + 2*i);
                        a0 = fma2(wA[2*i],   f0.x, a0);
                        a1 = fma2(wA[2*i+1], f0.y, a1);
                        a2 = fma2(wB[2*i],   f1.x, a2);
                        a3 = fma2(wB[2*i+1], f1.y, a3);
                    }
                    *o = mul2(add2(add2(a0, a1), add2(a2, a3)), pack2(s));
                } else *o = 0ull;
            }
        } else {
            #pragma unroll 2
            for (int r = 0; r < 32; r++){
                ull* o = obase + (size_t)r * 256;
                const float s = __shfl_sync(0xffffffffu, selv, r);
                if (act & (1u << r)){
                    const float2* feat = sFeat + (rb + r) * FSTRIDE + foff;
                    ull a0 = 0, a1 = 0, a2 = 0, a3 = 0;
                    #pragma unroll
                    for (int i = 0; i < 8; i++){
                        ulonglong2 f = *(const ulonglong2*)(feat + 2*i);
                        a0 = fma2(wA[2*i],   f.x, a0);
                        a1 = fma2(wA[2*i+1], f.y, a1);
                        a2 = fma2(wB[2*i],   f.x, a2);
                        a3 = fma2(wB[2*i+1], f.y, a3);
                    }
                    const ull sv = pack2(s);
                    o[dstA] = mul2(add2(a0, a1), sv);
                    o[dstB] = mul2(add2(a2, a3), sv);
                } else { o[dstA] = 0ull; o[dstB] = 0ull; }
            }
        }
    }
}

extern "C" void kernel_launch(void* const* d_in, const int* in_sizes, int n_in,
                              void* d_out, int out_size)
{
    const float* timestamp   = (const float*)d_in[0];
    const float* aux         = (const float*)d_in[1];
    const float* router_W    = (const float*)d_in[2];
    const float* router_b    = (const float*)d_in[3];
    const float* freqs       = (const float*)d_in[4];
    const float* fourier_W   = (const float*)d_in[5];
    const float* knots       = (const float*)d_in[6];
    const float* spline_W    = (const float*)d_in[7];
    const float* centers     = (const float*)d_in[8];
    const float* gauss_W     = (const float*)d_in[9];
    const float* wav_centers = (const float*)d_in[10];
    const float* wav_scales  = (const float*)d_in[11];
    const float* wavelet_W   = (const float*)d_in[12];
    float* out = (float*)d_out;

    const int B = in_sizes[0];

    mote_kernel<<<296, 320>>>(timestamp, aux, router_W, router_b, freqs,
                              fourier_W, knots, spline_W, centers, gauss_W,
                              wav_centers, wav_scales, wavelet_W, out, B);
}

// round 7
// speedup vs baseline: 1.5413x; 1.1827x over previous
#include <cuda_runtime.h>

typedef unsigned long long ull;

__device__ __forceinline__ ull fma2(ull a, ull b, ull c){
    ull d; asm("fma.rn.f32x2 %0, %1, %2, %3;" : "=l"(d) : "l"(a), "l"(b), "l"(c)); return d;
}
__device__ __forceinline__ ull add2(ull a, ull b){
    ull d; asm("add.rn.f32x2 %0, %1, %2;" : "=l"(d) : "l"(a), "l"(b)); return d;
}
__device__ __forceinline__ ull mul2(ull a, ull b){
    ull d; asm("mul.rn.f32x2 %0, %1, %2;" : "=l"(d) : "l"(a), "l"(b)); return d;
}
__device__ __forceinline__ ull pack2(float x){
    ull d; asm("mov.b64 %0, {%1, %1};" : "=l"(d) : "f"(x)); return d;
}
__device__ __forceinline__ ull packf2(float x, float y){
    ull d; asm("mov.b64 %0, {%1, %2};" : "=l"(d) : "f"(x), "f"(y)); return d;
}
__device__ __forceinline__ void unpack2(ull v, float& x, float& y){
    asm("mov.b64 {%0, %1}, %2;" : "=f"(x), "=f"(y) : "l"(v));
}

// E=4, D=128, G=16, KF=16 (freqs=1..16), KTOP=2.
// sFeat per row (stride 66 float2):
//   f2 [0..15]  : (sin_k, cos_k) pairs, k = 1..16   (NON-duplicated!)
//   f2 [16..31] : spline (v,v)   [32..47] : gauss (v,v)   [48..63] : wavelet (v,v)
// Phase 2: 10 warps = 2 row-streams x 5 jobs (32 fma2/row each, 8 LDS.128/row):
//   job0/1: fourier col-half; lane -> float cols (64j+2c, +1); packed sin/cos fma2,
//           horizontal add merges sin and cos partial sums. 1 STG.64/row.
//   job2/3/4: spline/gauss/wavelet full 128 cols; lane -> float4 col 4c. 1 STG.128/row.

#define FSTRIDE 66

__global__ __launch_bounds__(320, 2)
void mote_kernel(
    const float* __restrict__ timestamp,   // [B,1]
    const float* __restrict__ aux,         // [B,16]
    const float* __restrict__ router_W,    // [17,4]
    const float* __restrict__ router_b,    // [4]
    const float* __restrict__ freqs,       // [16]
    const float* __restrict__ fourier_W,   // [32,128]
    const float* __restrict__ knots,       // [16]
    const float* __restrict__ spline_W,    // [16,128]
    const float* __restrict__ centers,     // [16]
    const float* __restrict__ gauss_W,     // [16,128]
    const float* __restrict__ wav_centers, // [16]
    const float* __restrict__ wav_scales,  // [16]
    const float* __restrict__ wavelet_W,   // [16,128]
    float* __restrict__ out,
    int B)
{
    __shared__ __align__(16) float2 sFeat[64 * FSTRIDE];
    __shared__ float sDispP[4 * 64];     // planar dispatch weights [expert][row]
    __shared__ float sTime[64];

    const int tid  = threadIdx.x;
    const int wid  = tid >> 5;
    const int lane = tid & 31;

    // ---------------- phase-2 job setup (per warp) ----------------
    const int job  = wid % 5;
    const int strm = wid / 5;
    ull wA[16], wB[16];
    int cat = 0, foff = 0, dstA = 0;
    if (job < 2){
        // fourier: lane covers float cols cA = 64*job + 2*lane and cA+1.
        // wA[k] = (Ws_k[cA], Wc_k[cA]); wB[k] = (Ws_k[cA+1], Wc_k[cA+1])
        const int cA = 64 * job + 2 * lane;
        #pragma unroll
        for (int k = 0; k < 16; k++){
            wA[k] = packf2(fourier_W[k*128 + cA],     fourier_W[(16+k)*128 + cA]);
            wB[k] = packf2(fourier_W[k*128 + cA + 1], fourier_W[(16+k)*128 + cA + 1]);
        }
        dstA = 32 * job + lane;          // ull column index
    } else {
        cat  = job - 1;                  // 1=spline, 2=gauss, 3=wavelet
        foff = 16 * cat;                 // 16 / 32 / 48
        const float* Wexp = (cat == 1) ? spline_W : (cat == 2) ? gauss_W : wavelet_W;
        #pragma unroll
        for (int i = 0; i < 16; i++){
            wA[i] = ((const ull*)Wexp)[(size_t)i * 64 + 2*lane];
            wB[i] = ((const ull*)Wexp)[(size_t)i * 64 + 2*lane + 1];
        }
        dstA = cat * 64 + 2 * lane;      // ull column of float4 at col 4*lane
    }

    // ---------------- stage-B per-thread constants ----------------
    float bC = 0.f, bI = 0.f;
    if (wid == 4 || wid == 5)      bC = centers[(tid - 128) & 15];
    else if (wid >= 6){ int j = (tid - 192) & 15;
                        bC = wav_centers[j]; bI = __fdividef(1.f, wav_scales[j]); }

    // stage-A mapping: 4 threads per row, first 256 threads
    const int s4  = tid & 3;
    const int lr4 = tid >> 2;

    const size_t W_OFF = (size_t)B * 512;
    const size_t M_OFF = W_OFF + (size_t)B * 4;
    const int numBatches = B >> 6;
    const float E_M2 = 0.13533528324f;   // e^-2

    for (int batch = blockIdx.x; batch < numBatches; batch += gridDim.x){
        const int rowBase = batch << 6;
        __syncthreads();

        // ================= stage A: router + w/mask (tid < 256) =============
        if (tid < 256){
            const int row = rowBase + lr4;
            const float t = timestamp[row];
            if (s4 == 0) sTime[lr4] = t;

            const float4 xa = ((const float4*)(aux + (size_t)row * 16))[s4];
            const float* Wq = router_W + (1 + 4 * s4) * 4;
            float p0 = xa.x*Wq[0] + xa.y*Wq[4] + xa.z*Wq[8]  + xa.w*Wq[12];
            float p1 = xa.x*Wq[1] + xa.y*Wq[5] + xa.z*Wq[9]  + xa.w*Wq[13];
            float p2 = xa.x*Wq[2] + xa.y*Wq[6] + xa.z*Wq[10] + xa.w*Wq[14];
            float p3 = xa.x*Wq[3] + xa.y*Wq[7] + xa.z*Wq[11] + xa.w*Wq[15];
            if (s4 == 0){
                p0 += t*router_W[0] + router_b[0];
                p1 += t*router_W[1] + router_b[1];
                p2 += t*router_W[2] + router_b[2];
                p3 += t*router_W[3] + router_b[3];
            }
            p0 += __shfl_xor_sync(0xffffffffu, p0, 1);
            p1 += __shfl_xor_sync(0xffffffffu, p1, 1);
            p2 += __shfl_xor_sync(0xffffffffu, p2, 1);
            p3 += __shfl_xor_sync(0xffffffffu, p3, 1);
            p0 += __shfl_xor_sync(0xffffffffu, p0, 2);
            p1 += __shfl_xor_sync(0xffffffffu, p1, 2);
            p2 += __shfl_xor_sync(0xffffffffu, p2, 2);
            p3 += __shfl_xor_sync(0xffffffffu, p3, 2);

            float m  = fmaxf(fmaxf(p0, p1), fmaxf(p2, p3));
            float e0 = __expf(p0 - m), e1 = __expf(p1 - m);
            float e2 = __expf(p2 - m), e3 = __expf(p3 - m);
            float inv = __fdividef(1.0f, e0 + e1 + e2 + e3);
            float w0 = e0*inv, w1 = e1*inv, w2 = e2*inv, w3 = e3*inv;

            int r0 = (w1 >  w0) + (w2 >  w0) + (w3 >  w0);
            int r1 = (w0 >= w1) + (w2 >  w1) + (w3 >  w1);
            int r2 = (w0 >= w2) + (w1 >= w2) + (w3 >  w2);
            int r3 = (w0 >= w3) + (w1 >= w3) + (w2 >= w3);

            float ws = (s4==0) ? w0 : (s4==1) ? w1 : (s4==2) ? w2 : w3;
            int   rs = (s4==0) ? r0 : (s4==1) ? r1 : (s4==2) ? r2 : r3;
            sDispP[s4*64 + lr4] = (rs < 2) ? ws : 0.f;
            out[W_OFF + (size_t)row*4 + s4] = ws;
            out[M_OFF + (size_t)row*4 + s4] = (rs < 2) ? 1.0f : 0.0f;
        }
        __syncthreads();

        // ================= stage B: raw features, warp-specialized ==========
        if (wid < 2){
            // trig: thread = row; ladder; store (s,c) pairs, 2 per STS.128
            const int row = tid;
            const float t = sTime[row];
            float4* dst = (float4*)(sFeat + row * FSTRIDE);
            float s1 = __sinf(t), c1 = __cosf(t);
            float sk = s1, ck = c1;
            #pragma unroll
            for (int m2 = 0; m2 < 8; m2++){
                float sa = sk, ca = ck;
                float sb = fmaf(sa, c1,  ca * s1);
                float cb = fmaf(ca, c1, -sa * s1);
                dst[m2] = make_float4(sa, ca, sb, cb);
                sk = fmaf(sb, c1,  cb * s1);
                ck = fmaf(cb, c1, -sb * s1);
            }
        } else if (wid < 4){
            // spline: thread = row; anchored geometric-ratio chain, 3 MUFU
            const int row = tid - 64;
            const float t = sTime[row];
            float2* dst = sFeat + row * FSTRIDE + 16;
            const float a = (t + 2.0f) * 3.75f;
            int j0 = __float2int_rn(a);
            j0 = max(0, min(15, j0));
            const float d = a - (float)j0;
            const float f0 = __expf(-d * d);
            dst[j0] = make_float2(f0, f0);
            float f = f0, r = __expf(fmaf(2.0f, d, -1.0f));
            #pragma unroll
            for (int k = 1; k <= 15; k++){
                f *= r; r *= E_M2;
                if (j0 + k <= 15) dst[j0 + k] = make_float2(f, f);
            }
            f = f0; r = __expf(fmaf(-2.0f, d, -1.0f));
            #pragma unroll
            for (int k = 1; k <= 15; k++){
                f *= r; r *= E_M2;
                if (j0 - k >= 0) dst[j0 - k] = make_float2(f, f);
            }
        } else if (wid < 6){
            // gauss: thread = (feature j, 16-row block)
            const int tt = tid - 128;
            const int j  = tt & 15;
            const int r0 = (tt >> 4) << 4;
            #pragma unroll 4
            for (int k = 0; k < 16; k++){
                const int row = r0 + k;
                const float u = sTime[row] - bC;
                const float v = __expf(-u * u);
                sFeat[row * FSTRIDE + 32 + j] = make_float2(v, v);
            }
        } else {
            // wavelet: thread = (feature j, 8-row block), 4 warps
            const int tt = tid - 192;
            const int j  = tt & 15;
            const int r0 = (tt >> 4) << 3;
            #pragma unroll 4
            for (int k = 0; k < 8; k++){
                const int row = r0 + k;
                const float u  = (sTime[row] - bC) * bI;
                const float uu = u * u;
                const float v  = (1.0f - uu) * __expf(-0.5f * uu);
                sFeat[row * FSTRIDE + 48 + j] = make_float2(v, v);
            }
        }
        __syncthreads();

        // ================= phase 2: matvecs (warp = job, 32 rows/stream) ====
        const int rb = strm * 32;
        const float selv = sDispP[cat*64 + rb + lane];
        const unsigned act = __ballot_sync(0xffffffffu, selv != 0.f);
        ull* obase = (ull*)out + (size_t)(rowBase + rb) * 256 + dstA;

        if (job < 2){
            #pragma unroll 2
            for (int r = 0; r < 32; r++){
                ull* o = obase + (size_t)r * 256;
                const float s = __shfl_sync(0xffffffffu, selv, r);
                if (act & (1u << r)){
                    const float2* feat = sFeat + (rb + r) * FSTRIDE;
                    ull a0 = 0, a1 = 0, a2 = 0, a3 = 0;
                    #pragma unroll
                    for (int i = 0; i < 8; i++){
                        ulonglong2 F = *(const ulonglong2*)(feat + 2*i);
                        a0 = fma2(wA[2*i],   F.x, a0);
                        a1 = fma2(wA[2*i+1], F.y, a1);
                        a2 = fma2(wB[2*i],   F.x, a2);
                        a3 = fma2(wB[2*i+1], F.y, a3);
                    }
                    float lA, hA, lB, hB;
                    unpack2(add2(a0, a1), lA, hA);
                    unpack2(add2(a2, a3), lB, hB);
                    *o = packf2((lA + hA) * s, (lB + hB) * s);
                } else *o = 0ull;
            }
        } else {
            #pragma unroll 2
            for (int r = 0; r < 32; r++){
                ulonglong2* o = (ulonglong2*)(obase + (size_t)r * 256);
                const float s = __shfl_sync(0xffffffffu, selv, r);
                ulonglong2 res;
                if (act & (1u << r)){
                    const float2* feat = sFeat + (rb + r) * FSTRIDE + foff;
                    ull a0 = 0, a1 = 0, a2 = 0, a3 = 0;
                    #pragma unroll
                    for (int i = 0; i < 8; i++){
                        ulonglong2 F = *(const ulonglong2*)(feat + 2*i);
                        a0 = fma2(wA[2*i],   F.x, a0);
                        a1 = fma2(wA[2*i+1], F.y, a1);
                        a2 = fma2(wB[2*i],   F.x, a2);
                        a3 = fma2(wB[2*i+1], F.y, a3);
                    }
                    const ull sv = pack2(s);
                    res.x = mul2(add2(a0, a1), sv);
                    res.y = mul2(add2(a2, a3), sv);
                } else { res.x = 0ull; res.y = 0ull; }
                *o = res;
            }
        }
    }
}

extern "C" void kernel_launch(void* const* d_in, const int* in_sizes, int n_in,
                              void* d_out, int out_size)
{
    const float* timestamp   = (const float*)d_in[0];
    const float* aux         = (const float*)d_in[1];
    const float* router_W    = (const float*)d_in[2];
    const float* router_b    = (const float*)d_in[3];
    const float* freqs       = (const float*)d_in[4];
    const float* fourier_W   = (const float*)d_in[5];
    const float* knots       = (const float*)d_in[6];
    const float* spline_W    = (const float*)d_in[7];
    const float* centers     = (const float*)d_in[8];
    const float* gauss_W     = (const float*)d_in[9];
    const float* wav_centers = (const float*)d_in[10];
    const float* wav_scales  = (const float*)d_in[11];
    const float* wavelet_W   = (const float*)d_in[12];
    float* out = (float*)d_out;

    const int B = in_sizes[0];

    mote_kernel<<<296, 320>>>(timestamp, aux, router_W, router_b, freqs,
                              fourier_W, knots, spline_W, centers, gauss_W,
                              wav_centers, wav_scales, wavelet_W, out, B);
}